// round 12
// baseline (speedup 1.0000x reference)
#include <cuda_runtime.h>
#include <cuda_fp16.h>
#include <cstdint>
#include <cstddef>

// ---------------- problem constants ----------------
constexpr int B_SZ  = 8192;
constexpr int IN_SZ = 2048;
constexpr int H_SZ  = 2048;
constexpr int K_SZ  = IN_SZ + H_SZ;       // 4096
constexpr int N_SZ  = 4 * H_SZ;           // 8192 (gate-interleaved: n = 4h+g)

// GEMM tiling: CTA 128x128x64, warp tile 64x64, 128 threads, 2 CTAs/SM
constexpr int BM = 128, BN = 128, BK = 64;
constexpr int STAGES = 3;
constexpr int KT = K_SZ / BK;             // 64
constexpr int LDSP2 = 72;                 // padded fp16 per smem row (144B)
constexpr int STAGE_H_BYTES = 128 * LDSP2 * 2;        // 18432 per operand tile
constexpr int SMEM_BYTES = 2 * STAGES * STAGE_H_BYTES; // 110592
constexpr int NTHREADS = 128;             // 4 warps, 2x2 grid of 64x64 tiles

// epilogue staging pad (floats per row)
constexpr int EPAD = 40;

// static device scratch (fp16 operands only)
__device__ __half g_Ah[(size_t)B_SZ * K_SZ];           // 67 MB concat(input,h_prev)
__device__ __half g_Wh[(size_t)N_SZ * K_SZ];           // 67 MB gate-interleaved weights

#define DEVI __device__ __forceinline__

DEVI uint32_t smem_u32(const void* p) {
    uint32_t a;
    asm("{ .reg .u64 t; cvta.to.shared.u64 t, %1; cvt.u32.u64 %0, t; }"
        : "=r"(a) : "l"(p));
    return a;
}

DEVI void cp_async16(uint32_t dst, const void* src) {
    asm volatile("cp.async.cg.shared.global [%0], [%1], 16;"
                 :: "r"(dst), "l"(src) : "memory");
}
DEVI void cp_commit() { asm volatile("cp.async.commit_group;" ::: "memory"); }
template <int N> DEVI void cp_wait() {
    asm volatile("cp.async.wait_group %0;" :: "n"(N) : "memory");
}

DEVI void ldsm_x4(uint32_t r[4], uint32_t addr) {
    asm volatile("ldmatrix.sync.aligned.m8n8.x4.shared.b16 {%0,%1,%2,%3}, [%4];"
                 : "=r"(r[0]), "=r"(r[1]), "=r"(r[2]), "=r"(r[3]) : "r"(addr));
}

DEVI void mma_f16(float c[4], const uint32_t a[4], const uint32_t b0, const uint32_t b1) {
    asm volatile(
        "mma.sync.aligned.m16n8k16.row.col.f32.f16.f16.f32 "
        "{%0,%1,%2,%3},{%4,%5,%6,%7},{%8,%9},{%0,%1,%2,%3};"
        : "+f"(c[0]), "+f"(c[1]), "+f"(c[2]), "+f"(c[3])
        : "r"(a[0]), "r"(a[1]), "r"(a[2]), "r"(a[3]), "r"(b0), "r"(b1));
}

DEVI float fsig(float x) {
    float e = __expf(-x);
    float r;
    asm("rcp.approx.f32 %0, %1;" : "=f"(r) : "f"(1.0f + e));
    return r;
}
DEVI float ftanh_(float x) { return fmaf(2.0f, fsig(2.0f * x), -1.0f); }

// ---------------- merged prepass ----------------
constexpr int PREP_SPLIT = (int)(((size_t)B_SZ * K_SZ / 8) / 256);   // 16384

__global__ void __launch_bounds__(256)
prep_kernel(const float* __restrict__ inp, const float* __restrict__ hpv,
            const float* __restrict__ Wf, const float* __restrict__ Wi,
            const float* __restrict__ Wg, const float* __restrict__ Wo)
{
    const int b = blockIdx.x;
    if (b < PREP_SPLIT) {
        const size_t idx = (size_t)b * 256 + threadIdx.x;
        const int row  = (int)(idx >> 9);
        const int col8 = ((int)idx & 511) * 8;
        const float* src = (col8 < IN_SZ) ? (inp + (size_t)row * IN_SZ + col8)
                                          : (hpv + (size_t)row * H_SZ + (col8 - IN_SZ));
        float4 v0 = *(const float4*)src;
        float4 v1 = *(const float4*)(src + 4);
        __half2 h[4];
        h[0] = __floats2half2_rn(v0.x, v0.y);
        h[1] = __floats2half2_rn(v0.z, v0.w);
        h[2] = __floats2half2_rn(v1.x, v1.y);
        h[3] = __floats2half2_rn(v1.z, v1.w);
        *(uint4*)(g_Ah + (size_t)row * K_SZ + col8) = *(const uint4*)h;
    } else {
        const size_t idx = (size_t)(b - PREP_SPLIT) * 256 + threadIdx.x;
        const int row  = (int)(idx >> 9);           // out row = 4h+gate
        const int col8 = ((int)idx & 511) * 8;
        const int hrow = row >> 2;
        const int gate = row & 3;
        const float* W = (gate == 0) ? Wf : (gate == 1) ? Wi : (gate == 2) ? Wg : Wo;
        const float* src = W + (size_t)hrow * K_SZ + col8;
        float4 v0 = *(const float4*)src;
        float4 v1 = *(const float4*)(src + 4);
        __half2 h[4];
        h[0] = __floats2half2_rn(v0.x, v0.y);
        h[1] = __floats2half2_rn(v0.z, v0.w);
        h[2] = __floats2half2_rn(v1.x, v1.y);
        h[3] = __floats2half2_rn(v1.z, v1.w);
        *(uint4*)(g_Wh + (size_t)row * K_SZ + col8) = *(const uint4*)h;
    }
}

// ---------------- fused GEMM + LSTM (64x64 warp tile, reg-pipelined) ----------------
__global__ void __launch_bounds__(NTHREADS, 2)
lstm_fused_kernel(const float* __restrict__ c_prev,
                  const float* __restrict__ bf, const float* __restrict__ bi,
                  const float* __restrict__ bg, const float* __restrict__ bo,
                  float* __restrict__ out)
{
    extern __shared__ __half smh[];
    const uint32_t smA_u = smem_u32(smh);
    const uint32_t smB_u = smA_u + STAGES * STAGE_H_BYTES;

    const int tid  = threadIdx.x;
    const int lane = tid & 31;
    const int warp = tid >> 5;             // 0..3
    const int wm   = warp >> 1;            // 0..1 (M: 64-row half)
    const int wn   = warp & 1;             // 0..1 (N: 64-col half)

    constexpr int NT = N_SZ / BN;           // 64
    constexpr int GM = 8;
    const int bid   = blockIdx.x;
    const int group = bid / (GM * NT);
    const int rem   = bid % (GM * NT);
    const int mt    = group * GM + (rem % GM);
    const int nt    = rem / GM;
    const int m0  = mt * BM;
    const int n0  = nt * BN;
    const int h0g = nt * 32;

    auto load_stage = [&](int kt, int st) {
        const int kb = kt * BK;
        const uint32_t adst = smA_u + st * STAGE_H_BYTES;
        const uint32_t bdst = smB_u + st * STAGE_H_BYTES;
        #pragma unroll
        for (int i = 0; i < 8; ++i) {
            const int lin = tid + i * NTHREADS;       // 0..1023
            const int row = lin >> 3;                 // 0..127
            const int c8  = (lin & 7) * 8;
            cp_async16(adst + row * (LDSP2 * 2) + c8 * 2,
                       g_Ah + (size_t)(m0 + row) * K_SZ + kb + c8);
            cp_async16(bdst + row * (LDSP2 * 2) + c8 * 2,
                       g_Wh + (size_t)(n0 + row) * K_SZ + kb + c8);
        }
    };

    float acc[4][8][4];                    // mi(16-row) x ni(8-col) x frag
    #pragma unroll
    for (int a = 0; a < 4; ++a)
        #pragma unroll
        for (int b = 0; b < 8; ++b)
            #pragma unroll
            for (int c = 0; c < 4; ++c) acc[a][b][c] = 0.f;

    const int a_row = (lane & 15);
    const int a_col = (lane >> 4) * 8;
    const int b_row = (lane & 7) + (lane >> 4) * 8;
    const int b_col = ((lane >> 3) & 1) * 8;

    uint32_t fa[2][4][4], fb[2][4][4];     // double-buffered fragments

    auto load_frags = [&](int buf, uint32_t As, uint32_t Bs, int k0) {
        #pragma unroll
        for (int mi = 0; mi < 4; ++mi) {
            const int r = wm * 64 + mi * 16 + a_row;
            ldsm_x4(fa[buf][mi], As + (r * LDSP2 + k0 + a_col) * 2);
        }
        #pragma unroll
        for (int np = 0; np < 4; ++np) {
            const int r = wn * 64 + np * 16 + b_row;
            ldsm_x4(fb[buf][np], Bs + (r * LDSP2 + k0 + b_col) * 2);
        }
    };

    auto mma_all = [&](int buf) {
        #pragma unroll
        for (int mi = 0; mi < 4; ++mi) {
            #pragma unroll
            for (int np = 0; np < 4; ++np) {
                mma_f16(acc[mi][2 * np + 0], fa[buf][mi], fb[buf][np][0], fb[buf][np][1]);
                mma_f16(acc[mi][2 * np + 1], fa[buf][mi], fb[buf][np][2], fb[buf][np][3]);
            }
        }
    };

    // prologue: 2 stages in flight
    load_stage(0, 0); cp_commit();
    load_stage(1, 1); cp_commit();

    int rs = 0;
    for (int kt = 0; kt < KT; ++kt) {
        cp_wait<1>();                 // stage kt landed (mine)
        __syncthreads();              // publish all; slot kt-1 free

        if (kt + 2 < KT) load_stage(kt + 2, (kt + 2) % STAGES);
        cp_commit();

        const uint32_t As = smA_u + rs * STAGE_H_BYTES;
        const uint32_t Bs = smB_u + rs * STAGE_H_BYTES;

        load_frags(0, As, Bs, 0);     // ks0 (small bubble once per tile)
        load_frags(1, As, Bs, 16);    // prefetch ks1
        mma_all(0);                   // ks0
        load_frags(0, As, Bs, 32);    // prefetch ks2
        mma_all(1);                   // ks1
        load_frags(1, As, Bs, 48);    // prefetch ks3
        mma_all(0);                   // ks2
        mma_all(1);                   // ks3

        rs = (rs + 1 == STAGES) ? 0 : rs + 1;
    }

    // ================= fused LSTM epilogue =================
    __syncthreads();

    float* s_cpv = (float*)smh;             // [128][EPAD]
    float* s_h   = s_cpv + 128 * EPAD;
    float* s_c   = s_h   + 128 * EPAD;
    float* s_b   = s_c   + 128 * EPAD;      // [4][32]

    #pragma unroll
    for (int i = tid; i < 128 * 8; i += NTHREADS) {
        const int row = i >> 3, c4 = (i & 7) * 4;
        float4 v = *(const float4*)(c_prev + (size_t)(m0 + row) * H_SZ + h0g + c4);
        *(float4*)(s_cpv + row * EPAD + c4) = v;
    }
    if (tid < 32) {
        s_b[tid]      = bf[h0g + tid];
        s_b[32 + tid] = bi[h0g + tid];
        s_b[64 + tid] = bg[h0g + tid];
        s_b[96 + tid] = bo[h0g + tid];
    }
    __syncthreads();

    // lane pairing: lane&3 in {0,2} holds (f,i), {1,3} holds (g,o) of same h
    const int parity = lane & 1;
    #pragma unroll
    for (int ni = 0; ni < 8; ++ni) {
        const int h_loc = wn * 16 + ni * 2 + ((lane & 3) >> 1);
        const float vbf = s_b[h_loc];
        const float vbi = s_b[32 + h_loc];
        const float vbg = s_b[64 + h_loc];
        const float vbo = s_b[96 + h_loc];
        #pragma unroll
        for (int mi = 0; mi < 4; ++mi) {
            const float x0 = __shfl_xor_sync(0xffffffffu, acc[mi][ni][0], 1);
            const float x1 = __shfl_xor_sync(0xffffffffu, acc[mi][ni][1], 1);
            const float y0 = __shfl_xor_sync(0xffffffffu, acc[mi][ni][2], 1);
            const float y1 = __shfl_xor_sync(0xffffffffu, acc[mi][ni][3], 1);
            const float fpre = (parity ? y0 : acc[mi][ni][0]) + vbf;
            const float ipre = (parity ? y1 : acc[mi][ni][1]) + vbi;
            const float gpre = (parity ? acc[mi][ni][2] : x0) + vbg;
            const float opre = (parity ? acc[mi][ni][3] : x1) + vbo;

            const int row = wm * 64 + mi * 16 + (lane >> 2) + parity * 8;
            const float cp = s_cpv[row * EPAD + h_loc];
            const float f = fsig(fpre), ii = fsig(ipre);
            const float g = ftanh_(gpre), o = fsig(opre);
            const float cn = fmaf(f, cp, ii * g);
            const float hn = o * ftanh_(cn);
            s_h[row * EPAD + h_loc] = hn;
            s_c[row * EPAD + h_loc] = cn;
        }
    }
    __syncthreads();

    float* outh = out + (size_t)m0 * H_SZ + h0g;
    float* outc = out + (size_t)B_SZ * H_SZ + (size_t)m0 * H_SZ + h0g;
    #pragma unroll
    for (int i = tid; i < 128 * 8; i += NTHREADS) {
        const int row = i >> 3, c4 = (i & 7) * 4;
        *(float4*)(outh + (size_t)row * H_SZ + c4) = *(const float4*)(s_h + row * EPAD + c4);
        *(float4*)(outc + (size_t)row * H_SZ + c4) = *(const float4*)(s_c + row * EPAD + c4);
    }
}

// ---------------- host side ----------------
extern "C" void kernel_launch(void* const* d_in, const int* in_sizes, int n_in,
                              void* d_out, int out_size) {
    (void)in_sizes; (void)n_in; (void)out_size;
    const float* inp = (const float*)d_in[0];
    const float* hpv = (const float*)d_in[1];
    const float* cpv = (const float*)d_in[2];
    const float* Wf  = (const float*)d_in[3];
    const float* bf  = (const float*)d_in[4];
    const float* Wi  = (const float*)d_in[5];
    const float* bi  = (const float*)d_in[6];
    const float* Wg  = (const float*)d_in[7];
    const float* bg  = (const float*)d_in[8];
    const float* Wo  = (const float*)d_in[9];
    const float* bo  = (const float*)d_in[10];
    float* out = (float*)d_out;

    prep_kernel<<<2 * PREP_SPLIT, 256>>>(inp, hpv, Wf, Wi, Wg, Wo);

    cudaFuncSetAttribute(lstm_fused_kernel,
                         cudaFuncAttributeMaxDynamicSharedMemorySize, SMEM_BYTES);

    const int grid1 = (B_SZ / BM) * (N_SZ / BN);        // 4096
    lstm_fused_kernel<<<grid1, NTHREADS, SMEM_BYTES>>>(cpv, bf, bi, bg, bo, out);
}

// round 13
// speedup vs baseline: 1.0514x; 1.0514x over previous
#include <cuda_runtime.h>
#include <cuda_fp16.h>
#include <cstdint>
#include <cstddef>

// ---------------- problem constants ----------------
constexpr int B_SZ  = 8192;
constexpr int IN_SZ = 2048;
constexpr int H_SZ  = 2048;
constexpr int K_SZ  = IN_SZ + H_SZ;       // 4096
constexpr int N_SZ  = 4 * H_SZ;           // 8192 (gate-interleaved: n = 4h+g)

// GEMM tiling (fp16) — R7 champion config
constexpr int BM = 128, BN = 128, BK = 64;
constexpr int STAGES = 3;
constexpr int KT = K_SZ / BK;             // 64
constexpr int LDSP2 = 72;                 // padded fp16 per smem row (144B)
constexpr int STAGE_H_BYTES = 128 * LDSP2 * 2;        // 18432 per operand tile
constexpr int SMEM_BYTES = 2 * STAGES * STAGE_H_BYTES; // 110592

// epilogue staging pad (floats per row)
constexpr int EPAD = 40;

// static device scratch (fp16 operands only)
__device__ __half g_Ah[(size_t)B_SZ * K_SZ];           // 67 MB concat(input,h_prev)
__device__ __half g_Wh[(size_t)N_SZ * K_SZ];           // 67 MB gate-interleaved weights

#define DEVI __device__ __forceinline__

DEVI uint32_t smem_u32(const void* p) {
    uint32_t a;
    asm("{ .reg .u64 t; cvta.to.shared.u64 t, %1; cvt.u32.u64 %0, t; }"
        : "=r"(a) : "l"(p));
    return a;
}

DEVI void cp_async16(uint32_t dst, const void* src) {
    asm volatile("cp.async.cg.shared.global [%0], [%1], 16;"
                 :: "r"(dst), "l"(src) : "memory");
}
DEVI void cp_commit() { asm volatile("cp.async.commit_group;" ::: "memory"); }
template <int N> DEVI void cp_wait() {
    asm volatile("cp.async.wait_group %0;" :: "n"(N) : "memory");
}

DEVI void ldsm_x4(uint32_t r[4], uint32_t addr) {
    asm volatile("ldmatrix.sync.aligned.m8n8.x4.shared.b16 {%0,%1,%2,%3}, [%4];"
                 : "=r"(r[0]), "=r"(r[1]), "=r"(r[2]), "=r"(r[3]) : "r"(addr));
}

DEVI void mma_f16(float c[4], const uint32_t a[4], const uint32_t b0, const uint32_t b1) {
    asm volatile(
        "mma.sync.aligned.m16n8k16.row.col.f32.f16.f16.f32 "
        "{%0,%1,%2,%3},{%4,%5,%6,%7},{%8,%9},{%0,%1,%2,%3};"
        : "+f"(c[0]), "+f"(c[1]), "+f"(c[2]), "+f"(c[3])
        : "r"(a[0]), "r"(a[1]), "r"(a[2]), "r"(a[3]), "r"(b0), "r"(b1));
}

DEVI float fsig(float x) {
    float e = __expf(-x);
    float r;
    asm("rcp.approx.f32 %0, %1;" : "=f"(r) : "f"(1.0f + e));
    return r;
}
DEVI float ftanh_(float x) { return fmaf(2.0f, fsig(2.0f * x), -1.0f); }

// ---------------- merged prepass ----------------
constexpr int PREP_SPLIT = (int)(((size_t)B_SZ * K_SZ / 8) / 256);   // 16384

__global__ void __launch_bounds__(256)
prep_kernel(const float* __restrict__ inp, const float* __restrict__ hpv,
            const float* __restrict__ Wf, const float* __restrict__ Wi,
            const float* __restrict__ Wg, const float* __restrict__ Wo)
{
    const int b = blockIdx.x;
    if (b < PREP_SPLIT) {
        const size_t idx = (size_t)b * 256 + threadIdx.x;
        const int row  = (int)(idx >> 9);
        const int col8 = ((int)idx & 511) * 8;
        const float* src = (col8 < IN_SZ) ? (inp + (size_t)row * IN_SZ + col8)
                                          : (hpv + (size_t)row * H_SZ + (col8 - IN_SZ));
        float4 v0 = *(const float4*)src;
        float4 v1 = *(const float4*)(src + 4);
        __half2 h[4];
        h[0] = __floats2half2_rn(v0.x, v0.y);
        h[1] = __floats2half2_rn(v0.z, v0.w);
        h[2] = __floats2half2_rn(v1.x, v1.y);
        h[3] = __floats2half2_rn(v1.z, v1.w);
        *(uint4*)(g_Ah + (size_t)row * K_SZ + col8) = *(const uint4*)h;
    } else {
        const size_t idx = (size_t)(b - PREP_SPLIT) * 256 + threadIdx.x;
        const int row  = (int)(idx >> 9);           // out row = 4h+gate
        const int col8 = ((int)idx & 511) * 8;
        const int hrow = row >> 2;
        const int gate = row & 3;
        const float* W = (gate == 0) ? Wf : (gate == 1) ? Wi : (gate == 2) ? Wg : Wo;
        const float* src = W + (size_t)hrow * K_SZ + col8;
        float4 v0 = *(const float4*)src;
        float4 v1 = *(const float4*)(src + 4);
        __half2 h[4];
        h[0] = __floats2half2_rn(v0.x, v0.y);
        h[1] = __floats2half2_rn(v0.z, v0.w);
        h[2] = __floats2half2_rn(v1.x, v1.y);
        h[3] = __floats2half2_rn(v1.z, v1.w);
        *(uint4*)(g_Wh + (size_t)row * K_SZ + col8) = *(const uint4*)h;
    }
}

// ---------------- fused GEMM + LSTM kernel (R7 champion + reg-biases) ----------------
__global__ void __launch_bounds__(256, 2)
lstm_fused_kernel(const float* __restrict__ c_prev,
                  const float* __restrict__ bf, const float* __restrict__ bi,
                  const float* __restrict__ bg, const float* __restrict__ bo,
                  float* __restrict__ out)
{
    extern __shared__ __half smh[];
    const uint32_t smA_u = smem_u32(smh);
    const uint32_t smB_u = smA_u + STAGES * STAGE_H_BYTES;

    const int tid  = threadIdx.x;
    const int lane = tid & 31;
    const int warp = tid >> 5;
    const int wm   = warp >> 2;            // 0..1
    const int wn   = warp & 3;             // 0..3

    constexpr int NT = N_SZ / BN;           // 64
    constexpr int GM = 8;
    const int bid   = blockIdx.x;
    const int group = bid / (GM * NT);
    const int rem   = bid % (GM * NT);
    const int mt    = group * GM + (rem % GM);
    const int nt    = rem / GM;
    const int m0  = mt * BM;
    const int n0  = nt * BN;
    const int h0g = nt * 32;

    // per-thread bias preload (h column is fixed per thread): 4 regs, held
    // across the mainloop; removes epilogue smem staging of biases.
    const int h_base = h0g + wn * 8 + ((lane & 3) >> 1);
    float vbf0[4], vbi0[4], vbg0[4], vbo0[4];
    #pragma unroll
    for (int ni = 0; ni < 4; ++ni) {
        vbf0[ni] = bf[h_base + ni * 2];
        vbi0[ni] = bi[h_base + ni * 2];
        vbg0[ni] = bg[h_base + ni * 2];
        vbo0[ni] = bo[h_base + ni * 2];
    }

    auto load_stage = [&](int kt, int st) {
        const int kb = kt * BK;
        const uint32_t adst = smA_u + st * STAGE_H_BYTES;
        const uint32_t bdst = smB_u + st * STAGE_H_BYTES;
        #pragma unroll
        for (int i = 0; i < 4; ++i) {
            const int lin = tid + i * 256;
            const int row = lin >> 3;
            const int c8  = (lin & 7) * 8;
            cp_async16(adst + row * (LDSP2 * 2) + c8 * 2,
                       g_Ah + (size_t)(m0 + row) * K_SZ + kb + c8);
            cp_async16(bdst + row * (LDSP2 * 2) + c8 * 2,
                       g_Wh + (size_t)(n0 + row) * K_SZ + kb + c8);
        }
    };

    float acc[4][4][4];
    #pragma unroll
    for (int a = 0; a < 4; ++a)
        #pragma unroll
        for (int b = 0; b < 4; ++b)
            #pragma unroll
            for (int c = 0; c < 4; ++c) acc[a][b][c] = 0.f;

    load_stage(0, 0); cp_commit();
    load_stage(1, 1); cp_commit();

    const int a_row = (lane & 15);
    const int a_col = (lane >> 4) * 8;
    const int b_row = (lane & 7) + (lane >> 4) * 8;
    const int b_col = ((lane >> 3) & 1) * 8;

    int rs = 0;
    for (int kt = 0; kt < KT; ++kt) {
        cp_wait<STAGES - 2>();
        __syncthreads();

        if (kt + STAGES - 1 < KT) load_stage(kt + STAGES - 1, (kt + STAGES - 1) % STAGES);
        cp_commit();

        const uint32_t As = smA_u + rs * STAGE_H_BYTES;
        const uint32_t Bs = smB_u + rs * STAGE_H_BYTES;

        #pragma unroll
        for (int ks = 0; ks < 4; ++ks) {
            const int k0 = ks * 16;
            uint32_t af[4][4], bfm[2][4];
            #pragma unroll
            for (int mi = 0; mi < 4; ++mi) {
                const int r = wm * 64 + mi * 16 + a_row;
                ldsm_x4(af[mi], As + (r * LDSP2 + k0 + a_col) * 2);
            }
            #pragma unroll
            for (int np = 0; np < 2; ++np) {
                const int r = wn * 32 + np * 16 + b_row;
                ldsm_x4(bfm[np], Bs + (r * LDSP2 + k0 + b_col) * 2);
            }
            #pragma unroll
            for (int mi = 0; mi < 4; ++mi) {
                #pragma unroll
                for (int np = 0; np < 2; ++np) {
                    mma_f16(acc[mi][2 * np + 0], af[mi], bfm[np][0], bfm[np][1]);
                    mma_f16(acc[mi][2 * np + 1], af[mi], bfm[np][2], bfm[np][3]);
                }
            }
        }
        rs = (rs + 1 == STAGES) ? 0 : rs + 1;
    }

    // ================= fused LSTM epilogue =================
    __syncthreads();                        // mainloop smem reads complete

    float* s_cpv = (float*)smh;             // [128][EPAD]
    float* s_h   = s_cpv + 128 * EPAD;
    float* s_c   = s_h   + 128 * EPAD;

    #pragma unroll
    for (int i = tid; i < 128 * 8; i += 256) {
        const int row = i >> 3, c4 = (i & 7) * 4;
        float4 v = *(const float4*)(c_prev + (size_t)(m0 + row) * H_SZ + h0g + c4);
        *(float4*)(s_cpv + row * EPAD + c4) = v;
    }
    __syncthreads();

    // lane pairing: lane&3 in {0,2} holds (f,i), {1,3} holds (g,o) of same h
    const int parity = lane & 1;
    #pragma unroll
    for (int ni = 0; ni < 4; ++ni) {
        const int h_loc = wn * 8 + ni * 2 + ((lane & 3) >> 1);
        #pragma unroll
        for (int mi = 0; mi < 4; ++mi) {
            const float x0 = __shfl_xor_sync(0xffffffffu, acc[mi][ni][0], 1);
            const float x1 = __shfl_xor_sync(0xffffffffu, acc[mi][ni][1], 1);
            const float y0 = __shfl_xor_sync(0xffffffffu, acc[mi][ni][2], 1);
            const float y1 = __shfl_xor_sync(0xffffffffu, acc[mi][ni][3], 1);
            const float fpre = (parity ? y0 : acc[mi][ni][0]) + vbf0[ni];
            const float ipre = (parity ? y1 : acc[mi][ni][1]) + vbi0[ni];
            const float gpre = (parity ? acc[mi][ni][2] : x0) + vbg0[ni];
            const float opre = (parity ? acc[mi][ni][3] : x1) + vbo0[ni];

            const int row = wm * 64 + mi * 16 + (lane >> 2) + parity * 8;
            const float cp = s_cpv[row * EPAD + h_loc];
            const float f = fsig(fpre), ii = fsig(ipre);
            const float g = ftanh_(gpre), o = fsig(opre);
            const float cn = fmaf(f, cp, ii * g);
            const float hn = o * ftanh_(cn);
            s_h[row * EPAD + h_loc] = hn;
            s_c[row * EPAD + h_loc] = cn;
        }
    }
    __syncthreads();

    float* outh = out + (size_t)m0 * H_SZ + h0g;
    float* outc = out + (size_t)B_SZ * H_SZ + (size_t)m0 * H_SZ + h0g;
    #pragma unroll
    for (int i = tid; i < 128 * 8; i += 256) {
        const int row = i >> 3, c4 = (i & 7) * 4;
        *(float4*)(outh + (size_t)row * H_SZ + c4) = *(const float4*)(s_h + row * EPAD + c4);
        *(float4*)(outc + (size_t)row * H_SZ + c4) = *(const float4*)(s_c + row * EPAD + c4);
    }
}

// ---------------- host side ----------------
extern "C" void kernel_launch(void* const* d_in, const int* in_sizes, int n_in,
                              void* d_out, int out_size) {
    (void)in_sizes; (void)n_in; (void)out_size;
    const float* inp = (const float*)d_in[0];
    const float* hpv = (const float*)d_in[1];
    const float* cpv = (const float*)d_in[2];
    const float* Wf  = (const float*)d_in[3];
    const float* bf  = (const float*)d_in[4];
    const float* Wi  = (const float*)d_in[5];
    const float* bi  = (const float*)d_in[6];
    const float* Wg  = (const float*)d_in[7];
    const float* bg  = (const float*)d_in[8];
    const float* Wo  = (const float*)d_in[9];
    const float* bo  = (const float*)d_in[10];
    float* out = (float*)d_out;

    prep_kernel<<<2 * PREP_SPLIT, 256>>>(inp, hpv, Wf, Wi, Wg, Wo);

    cudaFuncSetAttribute(lstm_fused_kernel,
                         cudaFuncAttributeMaxDynamicSharedMemorySize, SMEM_BYTES);

    const int grid1 = (B_SZ / BM) * (N_SZ / BN);        // 4096
    lstm_fused_kernel<<<grid1, 256, SMEM_BYTES>>>(cpv, bf, bi, bg, bo, out);
}

// round 14
// speedup vs baseline: 1.0838x; 1.0308x over previous
#include <cuda_runtime.h>
#include <cuda_fp16.h>
#include <cstdint>
#include <cstddef>

// ---------------- problem constants ----------------
constexpr int B_SZ  = 8192;
constexpr int IN_SZ = 2048;
constexpr int H_SZ  = 2048;
constexpr int K_SZ  = IN_SZ + H_SZ;       // 4096
constexpr int N_SZ  = 4 * H_SZ;           // 8192 (gate-interleaved: n = 4h+g)

// GEMM tiling (fp16) — R7 champion config
constexpr int BM = 128, BN = 128, BK = 64;
constexpr int STAGES = 3;
constexpr int KT = K_SZ / BK;             // 64
constexpr int LDSP2 = 72;                 // padded fp16 per smem row (144B)
constexpr int STAGE_H_BYTES = 128 * LDSP2 * 2;        // 18432 per operand tile
constexpr int SMEM_BYTES = 2 * STAGES * STAGE_H_BYTES; // 110592

// epilogue staging pad (floats per row)
constexpr int EPAD = 40;

// static device scratch (fp16 operands only)
__device__ __half g_Ah[(size_t)B_SZ * K_SZ];           // 67 MB concat(input,h_prev)
__device__ __half g_Wh[(size_t)N_SZ * K_SZ];           // 67 MB gate-interleaved weights

#define DEVI __device__ __forceinline__

DEVI uint32_t smem_u32(const void* p) {
    uint32_t a;
    asm("{ .reg .u64 t; cvta.to.shared.u64 t, %1; cvt.u32.u64 %0, t; }"
        : "=r"(a) : "l"(p));
    return a;
}

DEVI void cp_async16(uint32_t dst, const void* src) {
    asm volatile("cp.async.cg.shared.global [%0], [%1], 16;"
                 :: "r"(dst), "l"(src) : "memory");
}
DEVI void cp_commit() { asm volatile("cp.async.commit_group;" ::: "memory"); }
template <int N> DEVI void cp_wait() {
    asm volatile("cp.async.wait_group %0;" :: "n"(N) : "memory");
}

DEVI void ldsm_x4(uint32_t r[4], uint32_t addr) {
    asm volatile("ldmatrix.sync.aligned.m8n8.x4.shared.b16 {%0,%1,%2,%3}, [%4];"
                 : "=r"(r[0]), "=r"(r[1]), "=r"(r[2]), "=r"(r[3]) : "r"(addr));
}

DEVI void mma_f16(float c[4], const uint32_t a[4], const uint32_t b0, const uint32_t b1) {
    asm volatile(
        "mma.sync.aligned.m16n8k16.row.col.f32.f16.f16.f32 "
        "{%0,%1,%2,%3},{%4,%5,%6,%7},{%8,%9},{%0,%1,%2,%3};"
        : "+f"(c[0]), "+f"(c[1]), "+f"(c[2]), "+f"(c[3])
        : "r"(a[0]), "r"(a[1]), "r"(a[2]), "r"(a[3]), "r"(b0), "r"(b1));
}

DEVI float fsig(float x) {
    float e = __expf(-x);
    float r;
    asm("rcp.approx.f32 %0, %1;" : "=f"(r) : "f"(1.0f + e));
    return r;
}
DEVI float ftanh_(float x) { return fmaf(2.0f, fsig(2.0f * x), -1.0f); }

// ---------------- merged prepass ----------------
constexpr int PREP_SPLIT = (int)(((size_t)B_SZ * K_SZ / 8) / 256);   // 16384

__global__ void __launch_bounds__(256)
prep_kernel(const float* __restrict__ inp, const float* __restrict__ hpv,
            const float* __restrict__ Wf, const float* __restrict__ Wi,
            const float* __restrict__ Wg, const float* __restrict__ Wo)
{
    const int b = blockIdx.x;
    if (b < PREP_SPLIT) {
        const size_t idx = (size_t)b * 256 + threadIdx.x;
        const int row  = (int)(idx >> 9);
        const int col8 = ((int)idx & 511) * 8;
        const float* src = (col8 < IN_SZ) ? (inp + (size_t)row * IN_SZ + col8)
                                          : (hpv + (size_t)row * H_SZ + (col8 - IN_SZ));
        float4 v0 = *(const float4*)src;
        float4 v1 = *(const float4*)(src + 4);
        __half2 h[4];
        h[0] = __floats2half2_rn(v0.x, v0.y);
        h[1] = __floats2half2_rn(v0.z, v0.w);
        h[2] = __floats2half2_rn(v1.x, v1.y);
        h[3] = __floats2half2_rn(v1.z, v1.w);
        *(uint4*)(g_Ah + (size_t)row * K_SZ + col8) = *(const uint4*)h;
    } else {
        const size_t idx = (size_t)(b - PREP_SPLIT) * 256 + threadIdx.x;
        const int row  = (int)(idx >> 9);           // out row = 4h+gate
        const int col8 = ((int)idx & 511) * 8;
        const int hrow = row >> 2;
        const int gate = row & 3;
        const float* W = (gate == 0) ? Wf : (gate == 1) ? Wi : (gate == 2) ? Wg : Wo;
        const float* src = W + (size_t)hrow * K_SZ + col8;
        float4 v0 = *(const float4*)src;
        float4 v1 = *(const float4*)(src + 4);
        __half2 h[4];
        h[0] = __floats2half2_rn(v0.x, v0.y);
        h[1] = __floats2half2_rn(v0.z, v0.w);
        h[2] = __floats2half2_rn(v1.x, v1.y);
        h[3] = __floats2half2_rn(v1.z, v1.w);
        *(uint4*)(g_Wh + (size_t)row * K_SZ + col8) = *(const uint4*)h;
    }
}

// ---------------- fused GEMM + LSTM kernel (R7 champion, GM=16) ----------------
__global__ void __launch_bounds__(256, 2)
lstm_fused_kernel(const float* __restrict__ c_prev,
                  const float* __restrict__ bf, const float* __restrict__ bi,
                  const float* __restrict__ bg, const float* __restrict__ bo,
                  float* __restrict__ out)
{
    extern __shared__ __half smh[];
    const uint32_t smA_u = smem_u32(smh);
    const uint32_t smB_u = smA_u + STAGES * STAGE_H_BYTES;

    const int tid  = threadIdx.x;
    const int lane = tid & 31;
    const int warp = tid >> 5;
    const int wm   = warp >> 2;            // 0..1
    const int wn   = warp & 3;             // 0..3

    constexpr int NT = N_SZ / BN;           // 64
    constexpr int GM = 16;                  // (only change vs champion: 8 -> 16)
    const int bid   = blockIdx.x;
    const int group = bid / (GM * NT);
    const int rem   = bid % (GM * NT);
    const int mt    = group * GM + (rem % GM);
    const int nt    = rem / GM;
    const int m0  = mt * BM;
    const int n0  = nt * BN;
    const int h0g = nt * 32;

    auto load_stage = [&](int kt, int st) {
        const int kb = kt * BK;
        const uint32_t adst = smA_u + st * STAGE_H_BYTES;
        const uint32_t bdst = smB_u + st * STAGE_H_BYTES;
        #pragma unroll
        for (int i = 0; i < 4; ++i) {
            const int lin = tid + i * 256;
            const int row = lin >> 3;
            const int c8  = (lin & 7) * 8;
            cp_async16(adst + row * (LDSP2 * 2) + c8 * 2,
                       g_Ah + (size_t)(m0 + row) * K_SZ + kb + c8);
            cp_async16(bdst + row * (LDSP2 * 2) + c8 * 2,
                       g_Wh + (size_t)(n0 + row) * K_SZ + kb + c8);
        }
    };

    float acc[4][4][4];
    #pragma unroll
    for (int a = 0; a < 4; ++a)
        #pragma unroll
        for (int b = 0; b < 4; ++b)
            #pragma unroll
            for (int c = 0; c < 4; ++c) acc[a][b][c] = 0.f;

    load_stage(0, 0); cp_commit();
    load_stage(1, 1); cp_commit();

    const int a_row = (lane & 15);
    const int a_col = (lane >> 4) * 8;
    const int b_row = (lane & 7) + (lane >> 4) * 8;
    const int b_col = ((lane >> 3) & 1) * 8;

    int rs = 0;
    for (int kt = 0; kt < KT; ++kt) {
        cp_wait<STAGES - 2>();
        __syncthreads();

        if (kt + STAGES - 1 < KT) load_stage(kt + STAGES - 1, (kt + STAGES - 1) % STAGES);
        cp_commit();

        const uint32_t As = smA_u + rs * STAGE_H_BYTES;
        const uint32_t Bs = smB_u + rs * STAGE_H_BYTES;

        #pragma unroll
        for (int ks = 0; ks < 4; ++ks) {
            const int k0 = ks * 16;
            uint32_t af[4][4], bfm[2][4];
            #pragma unroll
            for (int mi = 0; mi < 4; ++mi) {
                const int r = wm * 64 + mi * 16 + a_row;
                ldsm_x4(af[mi], As + (r * LDSP2 + k0 + a_col) * 2);
            }
            #pragma unroll
            for (int np = 0; np < 2; ++np) {
                const int r = wn * 32 + np * 16 + b_row;
                ldsm_x4(bfm[np], Bs + (r * LDSP2 + k0 + b_col) * 2);
            }
            #pragma unroll
            for (int mi = 0; mi < 4; ++mi) {
                #pragma unroll
                for (int np = 0; np < 2; ++np) {
                    mma_f16(acc[mi][2 * np + 0], af[mi], bfm[np][0], bfm[np][1]);
                    mma_f16(acc[mi][2 * np + 1], af[mi], bfm[np][2], bfm[np][3]);
                }
            }
        }
        rs = (rs + 1 == STAGES) ? 0 : rs + 1;
    }

    // ================= fused LSTM epilogue =================
    __syncthreads();                        // mainloop smem reads complete

    float* s_cpv = (float*)smh;             // [128][EPAD]
    float* s_h   = s_cpv + 128 * EPAD;
    float* s_c   = s_h   + 128 * EPAD;
    float* s_b   = s_c   + 128 * EPAD;      // [4][32]

    #pragma unroll
    for (int i = tid; i < 128 * 8; i += 256) {
        const int row = i >> 3, c4 = (i & 7) * 4;
        float4 v = *(const float4*)(c_prev + (size_t)(m0 + row) * H_SZ + h0g + c4);
        *(float4*)(s_cpv + row * EPAD + c4) = v;
    }
    if (tid < 32) {
        s_b[tid]      = bf[h0g + tid];
        s_b[32 + tid] = bi[h0g + tid];
        s_b[64 + tid] = bg[h0g + tid];
        s_b[96 + tid] = bo[h0g + tid];
    }
    __syncthreads();

    // lane pairing: lane&3 in {0,2} holds (f,i), {1,3} holds (g,o) of same h
    const int parity = lane & 1;
    #pragma unroll
    for (int ni = 0; ni < 4; ++ni) {
        const int h_loc = wn * 8 + ni * 2 + ((lane & 3) >> 1);
        const float vbf = s_b[h_loc];
        const float vbi = s_b[32 + h_loc];
        const float vbg = s_b[64 + h_loc];
        const float vbo = s_b[96 + h_loc];
        #pragma unroll
        for (int mi = 0; mi < 4; ++mi) {
            const float x0 = __shfl_xor_sync(0xffffffffu, acc[mi][ni][0], 1);
            const float x1 = __shfl_xor_sync(0xffffffffu, acc[mi][ni][1], 1);
            const float y0 = __shfl_xor_sync(0xffffffffu, acc[mi][ni][2], 1);
            const float y1 = __shfl_xor_sync(0xffffffffu, acc[mi][ni][3], 1);
            const float fpre = (parity ? y0 : acc[mi][ni][0]) + vbf;
            const float ipre = (parity ? y1 : acc[mi][ni][1]) + vbi;
            const float gpre = (parity ? acc[mi][ni][2] : x0) + vbg;
            const float opre = (parity ? acc[mi][ni][3] : x1) + vbo;

            const int row = wm * 64 + mi * 16 + (lane >> 2) + parity * 8;
            const float cp = s_cpv[row * EPAD + h_loc];
            const float f = fsig(fpre), ii = fsig(ipre);
            const float g = ftanh_(gpre), o = fsig(opre);
            const float cn = fmaf(f, cp, ii * g);
            const float hn = o * ftanh_(cn);
            s_h[row * EPAD + h_loc] = hn;
            s_c[row * EPAD + h_loc] = cn;
        }
    }
    __syncthreads();

    float* outh = out + (size_t)m0 * H_SZ + h0g;
    float* outc = out + (size_t)B_SZ * H_SZ + (size_t)m0 * H_SZ + h0g;
    #pragma unroll
    for (int i = tid; i < 128 * 8; i += 256) {
        const int row = i >> 3, c4 = (i & 7) * 4;
        *(float4*)(outh + (size_t)row * H_SZ + c4) = *(const float4*)(s_h + row * EPAD + c4);
        *(float4*)(outc + (size_t)row * H_SZ + c4) = *(const float4*)(s_c + row * EPAD + c4);
    }
}

// ---------------- host side ----------------
extern "C" void kernel_launch(void* const* d_in, const int* in_sizes, int n_in,
                              void* d_out, int out_size) {
    (void)in_sizes; (void)n_in; (void)out_size;
    const float* inp = (const float*)d_in[0];
    const float* hpv = (const float*)d_in[1];
    const float* cpv = (const float*)d_in[2];
    const float* Wf  = (const float*)d_in[3];
    const float* bf  = (const float*)d_in[4];
    const float* Wi  = (const float*)d_in[5];
    const float* bi  = (const float*)d_in[6];
    const float* Wg  = (const float*)d_in[7];
    const float* bg  = (const float*)d_in[8];
    const float* Wo  = (const float*)d_in[9];
    const float* bo  = (const float*)d_in[10];
    float* out = (float*)d_out;

    prep_kernel<<<2 * PREP_SPLIT, 256>>>(inp, hpv, Wf, Wi, Wg, Wo);

    cudaFuncSetAttribute(lstm_fused_kernel,
                         cudaFuncAttributeMaxDynamicSharedMemorySize, SMEM_BYTES);

    const int grid1 = (B_SZ / BM) * (N_SZ / BN);        // 4096
    lstm_fused_kernel<<<grid1, 256, SMEM_BYTES>>>(cpv, bf, bi, bg, bo, out);
}

// round 15
// speedup vs baseline: 1.0941x; 1.0095x over previous
#include <cuda_runtime.h>
#include <cuda_fp16.h>
#include <cstdint>
#include <cstddef>

// ---------------- problem constants ----------------
constexpr int B_SZ  = 8192;
constexpr int IN_SZ = 2048;
constexpr int H_SZ  = 2048;
constexpr int K_SZ  = IN_SZ + H_SZ;       // 4096
constexpr int N_SZ  = 4 * H_SZ;           // 8192 (gate-interleaved: n = 4h+g)

// GEMM tiling (fp16) — champion config (R7 shape, GM=16)
constexpr int BM = 128, BN = 128, BK = 64;
constexpr int STAGES = 3;
constexpr int KT = K_SZ / BK;             // 64
constexpr int LDSP2 = 72;                 // padded fp16 per smem row (144B)
constexpr int STAGE_H_BYTES = 128 * LDSP2 * 2;        // 18432 per operand tile
constexpr int SMEM_BYTES = 2 * STAGES * STAGE_H_BYTES; // 110592

// epilogue staging pad (floats per row)
constexpr int EPAD = 40;

// static device scratch (fp16 operands only)
__device__ __half g_Ah[(size_t)B_SZ * K_SZ];           // 67 MB concat(input,h_prev)
__device__ __half g_Wh[(size_t)N_SZ * K_SZ];           // 67 MB gate-interleaved weights

#define DEVI __device__ __forceinline__

DEVI uint32_t smem_u32(const void* p) {
    uint32_t a;
    asm("{ .reg .u64 t; cvta.to.shared.u64 t, %1; cvt.u32.u64 %0, t; }"
        : "=r"(a) : "l"(p));
    return a;
}

DEVI void cp_async16(uint32_t dst, const void* src) {
    asm volatile("cp.async.cg.shared.global [%0], [%1], 16;"
                 :: "r"(dst), "l"(src) : "memory");
}
DEVI void cp_commit() { asm volatile("cp.async.commit_group;" ::: "memory"); }
template <int N> DEVI void cp_wait() {
    asm volatile("cp.async.wait_group %0;" :: "n"(N) : "memory");
}

DEVI void ldsm_x4(uint32_t r[4], uint32_t addr) {
    asm volatile("ldmatrix.sync.aligned.m8n8.x4.shared.b16 {%0,%1,%2,%3}, [%4];"
                 : "=r"(r[0]), "=r"(r[1]), "=r"(r[2]), "=r"(r[3]) : "r"(addr));
}

DEVI void mma_f16(float c[4], const uint32_t a[4], const uint32_t b0, const uint32_t b1) {
    asm volatile(
        "mma.sync.aligned.m16n8k16.row.col.f32.f16.f16.f32 "
        "{%0,%1,%2,%3},{%4,%5,%6,%7},{%8,%9},{%0,%1,%2,%3};"
        : "+f"(c[0]), "+f"(c[1]), "+f"(c[2]), "+f"(c[3])
        : "r"(a[0]), "r"(a[1]), "r"(a[2]), "r"(a[3]), "r"(b0), "r"(b1));
}

DEVI float fsig(float x) {
    float e = __expf(-x);
    float r;
    asm("rcp.approx.f32 %0, %1;" : "=f"(r) : "f"(1.0f + e));
    return r;
}
DEVI float ftanh_(float x) { return fmaf(2.0f, fsig(2.0f * x), -1.0f); }

// ---------------- merged prepass ----------------
constexpr int PREP_SPLIT = (int)(((size_t)B_SZ * K_SZ / 8) / 256);   // 16384

__global__ void __launch_bounds__(256)
prep_kernel(const float* __restrict__ inp, const float* __restrict__ hpv,
            const float* __restrict__ Wf, const float* __restrict__ Wi,
            const float* __restrict__ Wg, const float* __restrict__ Wo)
{
    const int b = blockIdx.x;
    if (b < PREP_SPLIT) {
        const size_t idx = (size_t)b * 256 + threadIdx.x;
        const int row  = (int)(idx >> 9);
        const int col8 = ((int)idx & 511) * 8;
        const float* src = (col8 < IN_SZ) ? (inp + (size_t)row * IN_SZ + col8)
                                          : (hpv + (size_t)row * H_SZ + (col8 - IN_SZ));
        float4 v0 = *(const float4*)src;
        float4 v1 = *(const float4*)(src + 4);
        __half2 h[4];
        h[0] = __floats2half2_rn(v0.x, v0.y);
        h[1] = __floats2half2_rn(v0.z, v0.w);
        h[2] = __floats2half2_rn(v1.x, v1.y);
        h[3] = __floats2half2_rn(v1.z, v1.w);
        *(uint4*)(g_Ah + (size_t)row * K_SZ + col8) = *(const uint4*)h;
    } else {
        const size_t idx = (size_t)(b - PREP_SPLIT) * 256 + threadIdx.x;
        const int row  = (int)(idx >> 9);           // out row = 4h+gate
        const int col8 = ((int)idx & 511) * 8;
        const int hrow = row >> 2;
        const int gate = row & 3;
        const float* W = (gate == 0) ? Wf : (gate == 1) ? Wi : (gate == 2) ? Wg : Wo;
        const float* src = W + (size_t)hrow * K_SZ + col8;
        float4 v0 = *(const float4*)src;
        float4 v1 = *(const float4*)(src + 4);
        __half2 h[4];
        h[0] = __floats2half2_rn(v0.x, v0.y);
        h[1] = __floats2half2_rn(v0.z, v0.w);
        h[2] = __floats2half2_rn(v1.x, v1.y);
        h[3] = __floats2half2_rn(v1.z, v1.w);
        *(uint4*)(g_Wh + (size_t)row * K_SZ + col8) = *(const uint4*)h;
    }
}

// ---------------- fused GEMM + LSTM kernel (champion, cp.async epilogue) ----------------
__global__ void __launch_bounds__(256, 2)
lstm_fused_kernel(const float* __restrict__ c_prev,
                  const float* __restrict__ bf, const float* __restrict__ bi,
                  const float* __restrict__ bg, const float* __restrict__ bo,
                  float* __restrict__ out)
{
    extern __shared__ __half smh[];
    const uint32_t smA_u = smem_u32(smh);
    const uint32_t smB_u = smA_u + STAGES * STAGE_H_BYTES;

    const int tid  = threadIdx.x;
    const int lane = tid & 31;
    const int warp = tid >> 5;
    const int wm   = warp >> 2;            // 0..1
    const int wn   = warp & 3;             // 0..3

    constexpr int NT = N_SZ / BN;           // 64
    constexpr int GM = 16;
    const int bid   = blockIdx.x;
    const int group = bid / (GM * NT);
    const int rem   = bid % (GM * NT);
    const int mt    = group * GM + (rem % GM);
    const int nt    = rem / GM;
    const int m0  = mt * BM;
    const int n0  = nt * BN;
    const int h0g = nt * 32;

    auto load_stage = [&](int kt, int st) {
        const int kb = kt * BK;
        const uint32_t adst = smA_u + st * STAGE_H_BYTES;
        const uint32_t bdst = smB_u + st * STAGE_H_BYTES;
        #pragma unroll
        for (int i = 0; i < 4; ++i) {
            const int lin = tid + i * 256;
            const int row = lin >> 3;
            const int c8  = (lin & 7) * 8;
            cp_async16(adst + row * (LDSP2 * 2) + c8 * 2,
                       g_Ah + (size_t)(m0 + row) * K_SZ + kb + c8);
            cp_async16(bdst + row * (LDSP2 * 2) + c8 * 2,
                       g_Wh + (size_t)(n0 + row) * K_SZ + kb + c8);
        }
    };

    float acc[4][4][4];
    #pragma unroll
    for (int a = 0; a < 4; ++a)
        #pragma unroll
        for (int b = 0; b < 4; ++b)
            #pragma unroll
            for (int c = 0; c < 4; ++c) acc[a][b][c] = 0.f;

    load_stage(0, 0); cp_commit();
    load_stage(1, 1); cp_commit();

    const int a_row = (lane & 15);
    const int a_col = (lane >> 4) * 8;
    const int b_row = (lane & 7) + (lane >> 4) * 8;
    const int b_col = ((lane >> 3) & 1) * 8;

    int rs = 0;
    for (int kt = 0; kt < KT; ++kt) {
        cp_wait<STAGES - 2>();
        __syncthreads();

        if (kt + STAGES - 1 < KT) load_stage(kt + STAGES - 1, (kt + STAGES - 1) % STAGES);
        cp_commit();

        const uint32_t As = smA_u + rs * STAGE_H_BYTES;
        const uint32_t Bs = smB_u + rs * STAGE_H_BYTES;

        #pragma unroll
        for (int ks = 0; ks < 4; ++ks) {
            const int k0 = ks * 16;
            uint32_t af[4][4], bfm[2][4];
            #pragma unroll
            for (int mi = 0; mi < 4; ++mi) {
                const int r = wm * 64 + mi * 16 + a_row;
                ldsm_x4(af[mi], As + (r * LDSP2 + k0 + a_col) * 2);
            }
            #pragma unroll
            for (int np = 0; np < 2; ++np) {
                const int r = wn * 32 + np * 16 + b_row;
                ldsm_x4(bfm[np], Bs + (r * LDSP2 + k0 + b_col) * 2);
            }
            #pragma unroll
            for (int mi = 0; mi < 4; ++mi) {
                #pragma unroll
                for (int np = 0; np < 2; ++np) {
                    mma_f16(acc[mi][2 * np + 0], af[mi], bfm[np][0], bfm[np][1]);
                    mma_f16(acc[mi][2 * np + 1], af[mi], bfm[np][2], bfm[np][3]);
                }
            }
        }
        rs = (rs + 1 == STAGES) ? 0 : rs + 1;
    }

    // ================= fused LSTM epilogue =================
    __syncthreads();                        // mainloop smem reads complete

    float* s_cpv = (float*)smh;             // [128][EPAD]
    float* s_h   = s_cpv + 128 * EPAD;
    float* s_c   = s_h   + 128 * EPAD;
    float* s_b   = s_c   + 128 * EPAD;      // [4][32]
    const uint32_t s_cpv_u = smem_u32(s_cpv);

    // stage c_prev tile via cp.async (no register round-trip) + biases
    #pragma unroll
    for (int i = tid; i < 128 * 8; i += 256) {
        const int row = i >> 3, c4 = (i & 7) * 4;
        cp_async16(s_cpv_u + (row * EPAD + c4) * 4,
                   c_prev + (size_t)(m0 + row) * H_SZ + h0g + c4);
    }
    cp_commit();
    if (tid < 32) {
        s_b[tid]      = bf[h0g + tid];
        s_b[32 + tid] = bi[h0g + tid];
        s_b[64 + tid] = bg[h0g + tid];
        s_b[96 + tid] = bo[h0g + tid];
    }
    cp_wait<0>();
    __syncthreads();

    // lane pairing: lane&3 in {0,2} holds (f,i), {1,3} holds (g,o) of same h
    const int parity = lane & 1;
    #pragma unroll
    for (int ni = 0; ni < 4; ++ni) {
        const int h_loc = wn * 8 + ni * 2 + ((lane & 3) >> 1);
        const float vbf = s_b[h_loc];
        const float vbi = s_b[32 + h_loc];
        const float vbg = s_b[64 + h_loc];
        const float vbo = s_b[96 + h_loc];
        #pragma unroll
        for (int mi = 0; mi < 4; ++mi) {
            const float x0 = __shfl_xor_sync(0xffffffffu, acc[mi][ni][0], 1);
            const float x1 = __shfl_xor_sync(0xffffffffu, acc[mi][ni][1], 1);
            const float y0 = __shfl_xor_sync(0xffffffffu, acc[mi][ni][2], 1);
            const float y1 = __shfl_xor_sync(0xffffffffu, acc[mi][ni][3], 1);
            const float fpre = (parity ? y0 : acc[mi][ni][0]) + vbf;
            const float ipre = (parity ? y1 : acc[mi][ni][1]) + vbi;
            const float gpre = (parity ? acc[mi][ni][2] : x0) + vbg;
            const float opre = (parity ? acc[mi][ni][3] : x1) + vbo;

            const int row = wm * 64 + mi * 16 + (lane >> 2) + parity * 8;
            const float cp = s_cpv[row * EPAD + h_loc];
            const float f = fsig(fpre), ii = fsig(ipre);
            const float g = ftanh_(gpre), o = fsig(opre);
            const float cn = fmaf(f, cp, ii * g);
            const float hn = o * ftanh_(cn);
            s_h[row * EPAD + h_loc] = hn;
            s_c[row * EPAD + h_loc] = cn;
        }
    }
    __syncthreads();

    float* outh = out + (size_t)m0 * H_SZ + h0g;
    float* outc = out + (size_t)B_SZ * H_SZ + (size_t)m0 * H_SZ + h0g;
    #pragma unroll
    for (int i = tid; i < 128 * 8; i += 256) {
        const int row = i >> 3, c4 = (i & 7) * 4;
        *(float4*)(outh + (size_t)row * H_SZ + c4) = *(const float4*)(s_h + row * EPAD + c4);
        *(float4*)(outc + (size_t)row * H_SZ + c4) = *(const float4*)(s_c + row * EPAD + c4);
    }
}

// ---------------- host side ----------------
extern "C" void kernel_launch(void* const* d_in, const int* in_sizes, int n_in,
                              void* d_out, int out_size) {
    (void)in_sizes; (void)n_in; (void)out_size;
    const float* inp = (const float*)d_in[0];
    const float* hpv = (const float*)d_in[1];
    const float* cpv = (const float*)d_in[2];
    const float* Wf  = (const float*)d_in[3];
    const float* bf  = (const float*)d_in[4];
    const float* Wi  = (const float*)d_in[5];
    const float* bi  = (const float*)d_in[6];
    const float* Wg  = (const float*)d_in[7];
    const float* bg  = (const float*)d_in[8];
    const float* Wo  = (const float*)d_in[9];
    const float* bo  = (const float*)d_in[10];
    float* out = (float*)d_out;

    prep_kernel<<<2 * PREP_SPLIT, 256>>>(inp, hpv, Wf, Wi, Wg, Wo);

    cudaFuncSetAttribute(lstm_fused_kernel,
                         cudaFuncAttributeMaxDynamicSharedMemorySize, SMEM_BYTES);

    const int grid1 = (B_SZ / BM) * (N_SZ / BN);        // 4096
    lstm_fused_kernel<<<grid1, 256, SMEM_BYTES>>>(cpv, bf, bi, bg, bo, out);
}

// round 16
// speedup vs baseline: 1.0956x; 1.0014x over previous
#include <cuda_runtime.h>
#include <cuda_fp16.h>
#include <cstdint>
#include <cstddef>

// ---------------- problem constants ----------------
constexpr int B_SZ  = 8192;
constexpr int IN_SZ = 2048;
constexpr int H_SZ  = 2048;
constexpr int K_SZ  = IN_SZ + H_SZ;       // 4096
constexpr int N_SZ  = 4 * H_SZ;           // 8192 (gate-interleaved: n = 4h+g)

// GEMM tiling (fp16) — champion config (R7 shape, GM=16, cp.async epilogue)
constexpr int BM = 128, BN = 128, BK = 64;
constexpr int STAGES = 3;
constexpr int KT = K_SZ / BK;             // 64
constexpr int LDSP2 = 72;                 // padded fp16 per smem row (144B)
constexpr int STAGE_H_BYTES = 128 * LDSP2 * 2;        // 18432 per operand tile
constexpr int SMEM_BYTES = 2 * STAGES * STAGE_H_BYTES; // 110592

// epilogue staging pad (floats per row)
constexpr int EPAD = 40;

// static device scratch (fp16 operands only)
__device__ __half g_Ah[(size_t)B_SZ * K_SZ];           // 67 MB concat(input,h_prev)
__device__ __half g_Wh[(size_t)N_SZ * K_SZ];           // 67 MB gate-interleaved weights

#define DEVI __device__ __forceinline__

DEVI uint32_t smem_u32(const void* p) {
    uint32_t a;
    asm("{ .reg .u64 t; cvta.to.shared.u64 t, %1; cvt.u32.u64 %0, t; }"
        : "=r"(a) : "l"(p));
    return a;
}

DEVI void cp_async16(uint32_t dst, const void* src) {
    asm volatile("cp.async.cg.shared.global [%0], [%1], 16;"
                 :: "r"(dst), "l"(src) : "memory");
}
DEVI void cp_commit() { asm volatile("cp.async.commit_group;" ::: "memory"); }
template <int N> DEVI void cp_wait() {
    asm volatile("cp.async.wait_group %0;" :: "n"(N) : "memory");
}

DEVI void ldsm_x4(uint32_t r[4], uint32_t addr) {
    asm volatile("ldmatrix.sync.aligned.m8n8.x4.shared.b16 {%0,%1,%2,%3}, [%4];"
                 : "=r"(r[0]), "=r"(r[1]), "=r"(r[2]), "=r"(r[3]) : "r"(addr));
}

DEVI void mma_f16(float c[4], const uint32_t a[4], const uint32_t b0, const uint32_t b1) {
    asm volatile(
        "mma.sync.aligned.m16n8k16.row.col.f32.f16.f16.f32 "
        "{%0,%1,%2,%3},{%4,%5,%6,%7},{%8,%9},{%0,%1,%2,%3};"
        : "+f"(c[0]), "+f"(c[1]), "+f"(c[2]), "+f"(c[3])
        : "r"(a[0]), "r"(a[1]), "r"(a[2]), "r"(a[3]), "r"(b0), "r"(b1));
}

DEVI void stg_cs_f4(float* p, float4 v) {
    asm volatile("st.global.cs.v4.f32 [%0], {%1, %2, %3, %4};"
                 :: "l"(p), "f"(v.x), "f"(v.y), "f"(v.z), "f"(v.w) : "memory");
}

DEVI float fsig(float x) {
    float e = __expf(-x);
    float r;
    asm("rcp.approx.f32 %0, %1;" : "=f"(r) : "f"(1.0f + e));
    return r;
}
DEVI float ftanh_(float x) { return fmaf(2.0f, fsig(2.0f * x), -1.0f); }

// ---------------- merged prepass ----------------
constexpr int PREP_SPLIT = (int)(((size_t)B_SZ * K_SZ / 8) / 256);   // 16384

__global__ void __launch_bounds__(256)
prep_kernel(const float* __restrict__ inp, const float* __restrict__ hpv,
            const float* __restrict__ Wf, const float* __restrict__ Wi,
            const float* __restrict__ Wg, const float* __restrict__ Wo)
{
    const int b = blockIdx.x;
    if (b < PREP_SPLIT) {
        const size_t idx = (size_t)b * 256 + threadIdx.x;
        const int row  = (int)(idx >> 9);
        const int col8 = ((int)idx & 511) * 8;
        const float* src = (col8 < IN_SZ) ? (inp + (size_t)row * IN_SZ + col8)
                                          : (hpv + (size_t)row * H_SZ + (col8 - IN_SZ));
        float4 v0 = *(const float4*)src;
        float4 v1 = *(const float4*)(src + 4);
        __half2 h[4];
        h[0] = __floats2half2_rn(v0.x, v0.y);
        h[1] = __floats2half2_rn(v0.z, v0.w);
        h[2] = __floats2half2_rn(v1.x, v1.y);
        h[3] = __floats2half2_rn(v1.z, v1.w);
        *(uint4*)(g_Ah + (size_t)row * K_SZ + col8) = *(const uint4*)h;
    } else {
        const size_t idx = (size_t)(b - PREP_SPLIT) * 256 + threadIdx.x;
        const int row  = (int)(idx >> 9);           // out row = 4h+gate
        const int col8 = ((int)idx & 511) * 8;
        const int hrow = row >> 2;
        const int gate = row & 3;
        const float* W = (gate == 0) ? Wf : (gate == 1) ? Wi : (gate == 2) ? Wg : Wo;
        const float* src = W + (size_t)hrow * K_SZ + col8;
        float4 v0 = *(const float4*)src;
        float4 v1 = *(const float4*)(src + 4);
        __half2 h[4];
        h[0] = __floats2half2_rn(v0.x, v0.y);
        h[1] = __floats2half2_rn(v0.z, v0.w);
        h[2] = __floats2half2_rn(v1.x, v1.y);
        h[3] = __floats2half2_rn(v1.z, v1.w);
        *(uint4*)(g_Wh + (size_t)row * K_SZ + col8) = *(const uint4*)h;
    }
}

// ---------------- fused GEMM + LSTM kernel (champion + streaming stores) ----------------
__global__ void __launch_bounds__(256, 2)
lstm_fused_kernel(const float* __restrict__ c_prev,
                  const float* __restrict__ bf, const float* __restrict__ bi,
                  const float* __restrict__ bg, const float* __restrict__ bo,
                  float* __restrict__ out)
{
    extern __shared__ __half smh[];
    const uint32_t smA_u = smem_u32(smh);
    const uint32_t smB_u = smA_u + STAGES * STAGE_H_BYTES;

    const int tid  = threadIdx.x;
    const int lane = tid & 31;
    const int warp = tid >> 5;
    const int wm   = warp >> 2;            // 0..1
    const int wn   = warp & 3;             // 0..3

    constexpr int NT = N_SZ / BN;           // 64
    constexpr int GM = 16;
    const int bid   = blockIdx.x;
    const int group = bid / (GM * NT);
    const int rem   = bid % (GM * NT);
    const int mt    = group * GM + (rem % GM);
    const int nt    = rem / GM;
    const int m0  = mt * BM;
    const int n0  = nt * BN;
    const int h0g = nt * 32;

    auto load_stage = [&](int kt, int st) {
        const int kb = kt * BK;
        const uint32_t adst = smA_u + st * STAGE_H_BYTES;
        const uint32_t bdst = smB_u + st * STAGE_H_BYTES;
        #pragma unroll
        for (int i = 0; i < 4; ++i) {
            const int lin = tid + i * 256;
            const int row = lin >> 3;
            const int c8  = (lin & 7) * 8;
            cp_async16(adst + row * (LDSP2 * 2) + c8 * 2,
                       g_Ah + (size_t)(m0 + row) * K_SZ + kb + c8);
            cp_async16(bdst + row * (LDSP2 * 2) + c8 * 2,
                       g_Wh + (size_t)(n0 + row) * K_SZ + kb + c8);
        }
    };

    float acc[4][4][4];
    #pragma unroll
    for (int a = 0; a < 4; ++a)
        #pragma unroll
        for (int b = 0; b < 4; ++b)
            #pragma unroll
            for (int c = 0; c < 4; ++c) acc[a][b][c] = 0.f;

    load_stage(0, 0); cp_commit();
    load_stage(1, 1); cp_commit();

    const int a_row = (lane & 15);
    const int a_col = (lane >> 4) * 8;
    const int b_row = (lane & 7) + (lane >> 4) * 8;
    const int b_col = ((lane >> 3) & 1) * 8;

    int rs = 0;
    for (int kt = 0; kt < KT; ++kt) {
        cp_wait<STAGES - 2>();
        __syncthreads();

        if (kt + STAGES - 1 < KT) load_stage(kt + STAGES - 1, (kt + STAGES - 1) % STAGES);
        cp_commit();

        const uint32_t As = smA_u + rs * STAGE_H_BYTES;
        const uint32_t Bs = smB_u + rs * STAGE_H_BYTES;

        #pragma unroll
        for (int ks = 0; ks < 4; ++ks) {
            const int k0 = ks * 16;
            uint32_t af[4][4], bfm[2][4];
            #pragma unroll
            for (int mi = 0; mi < 4; ++mi) {
                const int r = wm * 64 + mi * 16 + a_row;
                ldsm_x4(af[mi], As + (r * LDSP2 + k0 + a_col) * 2);
            }
            #pragma unroll
            for (int np = 0; np < 2; ++np) {
                const int r = wn * 32 + np * 16 + b_row;
                ldsm_x4(bfm[np], Bs + (r * LDSP2 + k0 + b_col) * 2);
            }
            #pragma unroll
            for (int mi = 0; mi < 4; ++mi) {
                #pragma unroll
                for (int np = 0; np < 2; ++np) {
                    mma_f16(acc[mi][2 * np + 0], af[mi], bfm[np][0], bfm[np][1]);
                    mma_f16(acc[mi][2 * np + 1], af[mi], bfm[np][2], bfm[np][3]);
                }
            }
        }
        rs = (rs + 1 == STAGES) ? 0 : rs + 1;
    }

    // ================= fused LSTM epilogue =================
    __syncthreads();                        // mainloop smem reads complete

    float* s_cpv = (float*)smh;             // [128][EPAD]
    float* s_h   = s_cpv + 128 * EPAD;
    float* s_c   = s_h   + 128 * EPAD;
    float* s_b   = s_c   + 128 * EPAD;      // [4][32]
    const uint32_t s_cpv_u = smem_u32(s_cpv);

    // stage c_prev tile via cp.async (no register round-trip) + biases
    #pragma unroll
    for (int i = tid; i < 128 * 8; i += 256) {
        const int row = i >> 3, c4 = (i & 7) * 4;
        cp_async16(s_cpv_u + (row * EPAD + c4) * 4,
                   c_prev + (size_t)(m0 + row) * H_SZ + h0g + c4);
    }
    cp_commit();
    if (tid < 32) {
        s_b[tid]      = bf[h0g + tid];
        s_b[32 + tid] = bi[h0g + tid];
        s_b[64 + tid] = bg[h0g + tid];
        s_b[96 + tid] = bo[h0g + tid];
    }
    cp_wait<0>();
    __syncthreads();

    // lane pairing: lane&3 in {0,2} holds (f,i), {1,3} holds (g,o) of same h
    const int parity = lane & 1;
    #pragma unroll
    for (int ni = 0; ni < 4; ++ni) {
        const int h_loc = wn * 8 + ni * 2 + ((lane & 3) >> 1);
        const float vbf = s_b[h_loc];
        const float vbi = s_b[32 + h_loc];
        const float vbg = s_b[64 + h_loc];
        const float vbo = s_b[96 + h_loc];
        #pragma unroll
        for (int mi = 0; mi < 4; ++mi) {
            const float x0 = __shfl_xor_sync(0xffffffffu, acc[mi][ni][0], 1);
            const float x1 = __shfl_xor_sync(0xffffffffu, acc[mi][ni][1], 1);
            const float y0 = __shfl_xor_sync(0xffffffffu, acc[mi][ni][2], 1);
            const float y1 = __shfl_xor_sync(0xffffffffu, acc[mi][ni][3], 1);
            const float fpre = (parity ? y0 : acc[mi][ni][0]) + vbf;
            const float ipre = (parity ? y1 : acc[mi][ni][1]) + vbi;
            const float gpre = (parity ? acc[mi][ni][2] : x0) + vbg;
            const float opre = (parity ? acc[mi][ni][3] : x1) + vbo;

            const int row = wm * 64 + mi * 16 + (lane >> 2) + parity * 8;
            const float cp = s_cpv[row * EPAD + h_loc];
            const float f = fsig(fpre), ii = fsig(ipre);
            const float g = ftanh_(gpre), o = fsig(opre);
            const float cn = fmaf(f, cp, ii * g);
            const float hn = o * ftanh_(cn);
            s_h[row * EPAD + h_loc] = hn;
            s_c[row * EPAD + h_loc] = cn;
        }
    }
    __syncthreads();

    // streaming stores: output is write-once, keep it out of L2
    float* outh = out + (size_t)m0 * H_SZ + h0g;
    float* outc = out + (size_t)B_SZ * H_SZ + (size_t)m0 * H_SZ + h0g;
    #pragma unroll
    for (int i = tid; i < 128 * 8; i += 256) {
        const int row = i >> 3, c4 = (i & 7) * 4;
        stg_cs_f4(outh + (size_t)row * H_SZ + c4, *(const float4*)(s_h + row * EPAD + c4));
        stg_cs_f4(outc + (size_t)row * H_SZ + c4, *(const float4*)(s_c + row * EPAD + c4));
    }
}

// ---------------- host side ----------------
extern "C" void kernel_launch(void* const* d_in, const int* in_sizes, int n_in,
                              void* d_out, int out_size) {
    (void)in_sizes; (void)n_in; (void)out_size;
    const float* inp = (const float*)d_in[0];
    const float* hpv = (const float*)d_in[1];
    const float* cpv = (const float*)d_in[2];
    const float* Wf  = (const float*)d_in[3];
    const float* bf  = (const float*)d_in[4];
    const float* Wi  = (const float*)d_in[5];
    const float* bi  = (const float*)d_in[6];
    const float* Wg  = (const float*)d_in[7];
    const float* bg  = (const float*)d_in[8];
    const float* Wo  = (const float*)d_in[9];
    const float* bo  = (const float*)d_in[10];
    float* out = (float*)d_out;

    prep_kernel<<<2 * PREP_SPLIT, 256>>>(inp, hpv, Wf, Wi, Wg, Wo);

    cudaFuncSetAttribute(lstm_fused_kernel,
                         cudaFuncAttributeMaxDynamicSharedMemorySize, SMEM_BYTES);

    const int grid1 = (B_SZ / BM) * (N_SZ / BN);        // 4096
    lstm_fused_kernel<<<grid1, 256, SMEM_BYTES>>>(cpv, bf, bi, bg, bo, out);
}

// round 17
// speedup vs baseline: 1.1070x; 1.0105x over previous
#include <cuda_runtime.h>
#include <cuda_fp16.h>
#include <cstdint>
#include <cstddef>

// ---------------- problem constants ----------------
constexpr int B_SZ  = 8192;
constexpr int IN_SZ = 2048;
constexpr int H_SZ  = 2048;
constexpr int K_SZ  = IN_SZ + H_SZ;       // 4096
constexpr int N_SZ  = 4 * H_SZ;           // 8192 (gate-interleaved: n = 4h+g)

// GEMM tiling (fp16) — champion config (R7 shape, GM=16)
constexpr int BM = 128, BN = 128, BK = 64;
constexpr int STAGES = 3;
constexpr int KT = K_SZ / BK;             // 64
constexpr int LDSP2 = 72;                 // padded fp16 per smem row (144B)
constexpr int STAGE_H_BYTES = 128 * LDSP2 * 2;        // 18432 per operand tile
constexpr int SMEM_BYTES = 2 * STAGES * STAGE_H_BYTES; // 110592

// epilogue smem layout (liveness: stage-1 A/B free after kt=61; sync at kt=62 publishes)
constexpr int OFF_SH  = 0;        // s_h   [128][40] f32 (written post-mainloop)
constexpr int OFF_SB  = 20480;    // biases [4][32] f32 (stage1-A region, prefetched kt=62)
constexpr int OFF_SC  = 24576;    // s_c   [128][40] f32 (written post-mainloop)
constexpr int OFF_CPV = 73728;    // c_prev [128][36] f32 (stage1-B region, prefetched kt=62)
constexpr int EPAD = 40;
constexpr int CPAD = 36;

// static device scratch (fp16 operands only)
__device__ __half g_Ah[(size_t)B_SZ * K_SZ];           // 67 MB concat(input,h_prev)
__device__ __half g_Wh[(size_t)N_SZ * K_SZ];           // 67 MB gate-interleaved weights

#define DEVI __device__ __forceinline__

DEVI uint32_t smem_u32(const void* p) {
    uint32_t a;
    asm("{ .reg .u64 t; cvta.to.shared.u64 t, %1; cvt.u32.u64 %0, t; }"
        : "=r"(a) : "l"(p));
    return a;
}

DEVI void cp_async16(uint32_t dst, const void* src) {
    asm volatile("cp.async.cg.shared.global [%0], [%1], 16;"
                 :: "r"(dst), "l"(src) : "memory");
}
DEVI void cp_commit() { asm volatile("cp.async.commit_group;" ::: "memory"); }
template <int N> DEVI void cp_wait() {
    asm volatile("cp.async.wait_group %0;" :: "n"(N) : "memory");
}

DEVI void ldsm_x4(uint32_t r[4], uint32_t addr) {
    asm volatile("ldmatrix.sync.aligned.m8n8.x4.shared.b16 {%0,%1,%2,%3}, [%4];"
                 : "=r"(r[0]), "=r"(r[1]), "=r"(r[2]), "=r"(r[3]) : "r"(addr));
}

DEVI void mma_f16(float c[4], const uint32_t a[4], const uint32_t b0, const uint32_t b1) {
    asm volatile(
        "mma.sync.aligned.m16n8k16.row.col.f32.f16.f16.f32 "
        "{%0,%1,%2,%3},{%4,%5,%6,%7},{%8,%9},{%0,%1,%2,%3};"
        : "+f"(c[0]), "+f"(c[1]), "+f"(c[2]), "+f"(c[3])
        : "r"(a[0]), "r"(a[1]), "r"(a[2]), "r"(a[3]), "r"(b0), "r"(b1));
}

DEVI void stg_cs_f4(float* p, float4 v) {
    asm volatile("st.global.cs.v4.f32 [%0], {%1, %2, %3, %4};"
                 :: "l"(p), "f"(v.x), "f"(v.y), "f"(v.z), "f"(v.w) : "memory");
}

DEVI float fsig(float x) {
    float e = __expf(-x);
    float r;
    asm("rcp.approx.f32 %0, %1;" : "=f"(r) : "f"(1.0f + e));
    return r;
}
DEVI float ftanh_(float x) { return fmaf(2.0f, fsig(2.0f * x), -1.0f); }

// ---------------- merged prepass ----------------
constexpr int PREP_SPLIT = (int)(((size_t)B_SZ * K_SZ / 8) / 256);   // 16384

__global__ void __launch_bounds__(256)
prep_kernel(const float* __restrict__ inp, const float* __restrict__ hpv,
            const float* __restrict__ Wf, const float* __restrict__ Wi,
            const float* __restrict__ Wg, const float* __restrict__ Wo)
{
    const int b = blockIdx.x;
    if (b < PREP_SPLIT) {
        const size_t idx = (size_t)b * 256 + threadIdx.x;
        const int row  = (int)(idx >> 9);
        const int col8 = ((int)idx & 511) * 8;
        const float* src = (col8 < IN_SZ) ? (inp + (size_t)row * IN_SZ + col8)
                                          : (hpv + (size_t)row * H_SZ + (col8 - IN_SZ));
        float4 v0 = *(const float4*)src;
        float4 v1 = *(const float4*)(src + 4);
        __half2 h[4];
        h[0] = __floats2half2_rn(v0.x, v0.y);
        h[1] = __floats2half2_rn(v0.z, v0.w);
        h[2] = __floats2half2_rn(v1.x, v1.y);
        h[3] = __floats2half2_rn(v1.z, v1.w);
        *(uint4*)(g_Ah + (size_t)row * K_SZ + col8) = *(const uint4*)h;
    } else {
        const size_t idx = (size_t)(b - PREP_SPLIT) * 256 + threadIdx.x;
        const int row  = (int)(idx >> 9);           // out row = 4h+gate
        const int col8 = ((int)idx & 511) * 8;
        const int hrow = row >> 2;
        const int gate = row & 3;
        const float* W = (gate == 0) ? Wf : (gate == 1) ? Wi : (gate == 2) ? Wg : Wo;
        const float* src = W + (size_t)hrow * K_SZ + col8;
        float4 v0 = *(const float4*)src;
        float4 v1 = *(const float4*)(src + 4);
        __half2 h[4];
        h[0] = __floats2half2_rn(v0.x, v0.y);
        h[1] = __floats2half2_rn(v0.z, v0.w);
        h[2] = __floats2half2_rn(v1.x, v1.y);
        h[3] = __floats2half2_rn(v1.z, v1.w);
        *(uint4*)(g_Wh + (size_t)row * K_SZ + col8) = *(const uint4*)h;
    }
}

// ---------------- fused GEMM + LSTM kernel (peeled-tail prefetch) ----------------
__global__ void __launch_bounds__(256, 2)
lstm_fused_kernel(const float* __restrict__ c_prev,
                  const float* __restrict__ bf, const float* __restrict__ bi,
                  const float* __restrict__ bg, const float* __restrict__ bo,
                  float* __restrict__ out)
{
    extern __shared__ __half smh[];
    char* smc = (char*)smh;
    const uint32_t smA_u = smem_u32(smh);
    const uint32_t smB_u = smA_u + STAGES * STAGE_H_BYTES;

    const int tid  = threadIdx.x;
    const int lane = tid & 31;
    const int warp = tid >> 5;
    const int wm   = warp >> 2;            // 0..1
    const int wn   = warp & 3;             // 0..3

    constexpr int NT = N_SZ / BN;           // 64
    constexpr int GM = 16;
    const int bid   = blockIdx.x;
    const int group = bid / (GM * NT);
    const int rem   = bid % (GM * NT);
    const int mt    = group * GM + (rem % GM);
    const int nt    = rem / GM;
    const int m0  = mt * BM;
    const int n0  = nt * BN;
    const int h0g = nt * 32;

    auto load_stage = [&](int kt, int st) {
        const int kb = kt * BK;
        const uint32_t adst = smA_u + st * STAGE_H_BYTES;
        const uint32_t bdst = smB_u + st * STAGE_H_BYTES;
        #pragma unroll
        for (int i = 0; i < 4; ++i) {
            const int lin = tid + i * 256;
            const int row = lin >> 3;
            const int c8  = (lin & 7) * 8;
            cp_async16(adst + row * (LDSP2 * 2) + c8 * 2,
                       g_Ah + (size_t)(m0 + row) * K_SZ + kb + c8);
            cp_async16(bdst + row * (LDSP2 * 2) + c8 * 2,
                       g_Wh + (size_t)(n0 + row) * K_SZ + kb + c8);
        }
    };

    float acc[4][4][4];
    #pragma unroll
    for (int a = 0; a < 4; ++a)
        #pragma unroll
        for (int b = 0; b < 4; ++b)
            #pragma unroll
            for (int c = 0; c < 4; ++c) acc[a][b][c] = 0.f;

    load_stage(0, 0); cp_commit();
    load_stage(1, 1); cp_commit();

    const int a_row = (lane & 15);
    const int a_col = (lane >> 4) * 8;
    const int b_row = (lane & 7) + (lane >> 4) * 8;
    const int b_col = ((lane >> 3) & 1) * 8;

    auto mma_tile = [&](int rs) {
        const uint32_t As = smA_u + rs * STAGE_H_BYTES;
        const uint32_t Bs = smB_u + rs * STAGE_H_BYTES;
        #pragma unroll
        for (int ks = 0; ks < 4; ++ks) {
            const int k0 = ks * 16;
            uint32_t af[4][4], bfm[2][4];
            #pragma unroll
            for (int mi = 0; mi < 4; ++mi) {
                const int r = wm * 64 + mi * 16 + a_row;
                ldsm_x4(af[mi], As + (r * LDSP2 + k0 + a_col) * 2);
            }
            #pragma unroll
            for (int np = 0; np < 2; ++np) {
                const int r = wn * 32 + np * 16 + b_row;
                ldsm_x4(bfm[np], Bs + (r * LDSP2 + k0 + b_col) * 2);
            }
            #pragma unroll
            for (int mi = 0; mi < 4; ++mi) {
                #pragma unroll
                for (int np = 0; np < 2; ++np) {
                    mma_f16(acc[mi][2 * np + 0], af[mi], bfm[np][0], bfm[np][1]);
                    mma_f16(acc[mi][2 * np + 1], af[mi], bfm[np][2], bfm[np][3]);
                }
            }
        }
    };

    // hot loop: branch-free, always loads kt+2
    int rs = 0;
    for (int kt = 0; kt < KT - 2; ++kt) {
        cp_wait<STAGES - 2>();
        __syncthreads();
        load_stage(kt + 2, (kt + 2) % STAGES);
        cp_commit();
        mma_tile(rs);
        rs = (rs + 1 == STAGES) ? 0 : rs + 1;
    }

    // peeled kt = KT-2: dead load slot -> prefetch epilogue operands into
    // stage-1 regions (last read at kt = KT-3; the barrier below publishes).
    cp_wait<STAGES - 2>();
    __syncthreads();
    {
        #pragma unroll
        for (int i = 0; i < 4; ++i) {
            const int lin = tid + i * 256;            // 128 rows x 8 float4
            const int row = lin >> 3;
            const int c4  = (lin & 7) * 4;
            cp_async16(smA_u + OFF_CPV + (row * CPAD + c4) * 4,
                       c_prev + (size_t)(m0 + row) * H_SZ + h0g + c4);
        }
        if (tid < 32) {
            const int g = tid >> 3, idx = (tid & 7) * 4;
            const float* bsrc = (g == 0) ? bf : (g == 1) ? bi : (g == 2) ? bg : bo;
            cp_async16(smA_u + OFF_SB + g * 128 + idx * 4, bsrc + h0g + idx);
        }
    }
    cp_commit();
    mma_tile(rs);
    rs = (rs + 1 == STAGES) ? 0 : rs + 1;

    // peeled kt = KT-1: drains the last stage copy, leaves epilogue group pending
    cp_wait<STAGES - 2>();
    __syncthreads();
    mma_tile(rs);

    // ================= fused LSTM epilogue =================
    cp_wait<0>();                            // epilogue operands landed (long ago)
    __syncthreads();                         // mainloop smem reads complete

    float* s_h   = (float*)(smc + OFF_SH);   // [128][EPAD]
    float* s_b   = (float*)(smc + OFF_SB);   // [4][32]
    float* s_c   = (float*)(smc + OFF_SC);   // [128][EPAD]
    float* s_cpv = (float*)(smc + OFF_CPV);  // [128][CPAD]

    // lane pairing: lane&3 in {0,2} holds (f,i), {1,3} holds (g,o) of same h
    const int parity = lane & 1;
    #pragma unroll
    for (int ni = 0; ni < 4; ++ni) {
        const int h_loc = wn * 8 + ni * 2 + ((lane & 3) >> 1);
        const float vbf = s_b[h_loc];
        const float vbi = s_b[32 + h_loc];
        const float vbg = s_b[64 + h_loc];
        const float vbo = s_b[96 + h_loc];
        #pragma unroll
        for (int mi = 0; mi < 4; ++mi) {
            const float x0 = __shfl_xor_sync(0xffffffffu, acc[mi][ni][0], 1);
            const float x1 = __shfl_xor_sync(0xffffffffu, acc[mi][ni][1], 1);
            const float y0 = __shfl_xor_sync(0xffffffffu, acc[mi][ni][2], 1);
            const float y1 = __shfl_xor_sync(0xffffffffu, acc[mi][ni][3], 1);
            const float fpre = (parity ? y0 : acc[mi][ni][0]) + vbf;
            const float ipre = (parity ? y1 : acc[mi][ni][1]) + vbi;
            const float gpre = (parity ? acc[mi][ni][2] : x0) + vbg;
            const float opre = (parity ? acc[mi][ni][3] : x1) + vbo;

            const int row = wm * 64 + mi * 16 + (lane >> 2) + parity * 8;
            const float cp = s_cpv[row * CPAD + h_loc];
            const float f = fsig(fpre), ii = fsig(ipre);
            const float g = ftanh_(gpre), o = fsig(opre);
            const float cn = fmaf(f, cp, ii * g);
            const float hn = o * ftanh_(cn);
            s_h[row * EPAD + h_loc] = hn;
            s_c[row * EPAD + h_loc] = cn;
        }
    }
    __syncthreads();

    // streaming stores: output is write-once, keep it out of L2
    float* outh = out + (size_t)m0 * H_SZ + h0g;
    float* outc = out + (size_t)B_SZ * H_SZ + (size_t)m0 * H_SZ + h0g;
    #pragma unroll
    for (int i = tid; i < 128 * 8; i += 256) {
        const int row = i >> 3, c4 = (i & 7) * 4;
        stg_cs_f4(outh + (size_t)row * H_SZ + c4, *(const float4*)(s_h + row * EPAD + c4));
        stg_cs_f4(outc + (size_t)row * H_SZ + c4, *(const float4*)(s_c + row * EPAD + c4));
    }
}

// ---------------- host side ----------------
extern "C" void kernel_launch(void* const* d_in, const int* in_sizes, int n_in,
                              void* d_out, int out_size) {
    (void)in_sizes; (void)n_in; (void)out_size;
    const float* inp = (const float*)d_in[0];
    const float* hpv = (const float*)d_in[1];
    const float* cpv = (const float*)d_in[2];
    const float* Wf  = (const float*)d_in[3];
    const float* bf  = (const float*)d_in[4];
    const float* Wi  = (const float*)d_in[5];
    const float* bi  = (const float*)d_in[6];
    const float* Wg  = (const float*)d_in[7];
    const float* bg  = (const float*)d_in[8];
    const float* Wo  = (const float*)d_in[9];
    const float* bo  = (const float*)d_in[10];
    float* out = (float*)d_out;

    prep_kernel<<<2 * PREP_SPLIT, 256>>>(inp, hpv, Wf, Wi, Wg, Wo);

    cudaFuncSetAttribute(lstm_fused_kernel,
                         cudaFuncAttributeMaxDynamicSharedMemorySize, SMEM_BYTES);

    const int grid1 = (B_SZ / BM) * (N_SZ / BN);        // 4096
    lstm_fused_kernel<<<grid1, 256, SMEM_BYTES>>>(cpv, bf, bi, bg, bo, out);
}